// round 14
// baseline (speedup 1.0000x reference)
#include <cuda_runtime.h>
#include <cuda_fp16.h>
#include <cstdint>

// ---------------- problem constants ----------------
#define BATCH 4
#define SEQ 2048
#define EMB 2048
#define NH 16
#define DH 128
#define BH (BATCH * NH)          // 64
#define SD (SEQ * DH)            // 262144
#define SS ((size_t)SEQ * SEQ)
#define INVSQ 0.08838834764831845f   // 1/sqrt(128)

// scratch (allocation-free rule) — all fp16 except stats
__device__ __half g_xh[(size_t)BATCH * SEQ * EMB];
__device__ __half g_wh[4][(size_t)EMB * EMB];
__device__ __half g_qh[(size_t)BH * SD];
__device__ __half g_kh[(size_t)BH * SD];
__device__ __half g_vh[(size_t)BH * SD];
__device__ __half g_vth[(size_t)BH * SD];           // V transposed: [bh][dh][seq]
__device__ __half g_sh[(size_t)BH * SS];            // raw scores
__device__ __half g_ctxh[(size_t)BATCH * SEQ * EMB];
__device__ float g_m[(size_t)BH * SEQ];
__device__ float g_l[(size_t)BH * SEQ];
__device__ float g_pm[(size_t)BH * 16 * SEQ];
__device__ float g_pl[(size_t)BH * 16 * SEQ];

__device__ __forceinline__ uint32_t smem_u32(const void* p) {
    return (uint32_t)__cvta_generic_to_shared(p);
}
__device__ __forceinline__ void cp16(uint32_t s, const void* g) {
    asm volatile("cp.async.cg.shared.global [%0], [%1], 16;\n" :: "r"(s), "l"(g));
}
__device__ __forceinline__ void ldsm4(uint32_t* r, uint32_t addr) {
    asm volatile("ldmatrix.sync.aligned.m8n8.x4.shared.b16 {%0,%1,%2,%3}, [%4];"
                 : "=r"(r[0]), "=r"(r[1]), "=r"(r[2]), "=r"(r[3]) : "r"(addr));
}
__device__ __forceinline__ void mma_f16(float* c, const uint32_t* a, const uint32_t* b) {
    asm volatile(
        "mma.sync.aligned.m16n8k16.row.col.f32.f16.f16.f32 "
        "{%0,%1,%2,%3},{%4,%5,%6,%7},{%8,%9},{%0,%1,%2,%3};"
        : "+f"(c[0]), "+f"(c[1]), "+f"(c[2]), "+f"(c[3])
        : "r"(a[0]), "r"(a[1]), "r"(a[2]), "r"(a[3]), "r"(b[0]), "r"(b[1]));
}

// ---------------------------------------------------------------------------
// FP16 mma.sync GEMM (fp32 accum), CTA 128x128, 256 threads = 8 warps (4m x 2n),
// warp tile 32x64, BK=32, 3-stage cp.async pipeline, ldmatrix operands.
// MODE 0: fused QKV proj; grid.x=48: sel=bx>>4 picks Wq/Wk/Wv, head=bx&15.
// MODE 2: ctx = softmax(S) V per (b,h); exp+mask fused into A fragments,
//         B = pre-transposed g_vth, K truncated causally.
// MODE 3: out proj C = ctx * Wo^T + bias, fp32 out.
// (scores are handled by scores_rowpanel below)
// ---------------------------------------------------------------------------
#define BK 32
#define SA_H 40                                 // tile row stride (halves)
#define B_OFF_H (128 * SA_H)                    // halves
#define STAGE_H (2 * 128 * SA_H)                // 10240 halves = 20480 B
#define NSTAGE 3
#define SMEM_BYTES (NSTAGE * STAGE_H * 2)       // 61440

template<int MODE>
__global__ __launch_bounds__(256, 2)
void gemm_tc(float* __restrict__ Oext, const float* __restrict__ bias)
{
    extern __shared__ __align__(16) char dynRaw[];
    __half* dynh = (__half*)dynRaw;

    const int tid  = threadIdx.x;
    const int wid  = tid >> 5;
    const int lane = tid & 31;
    const int wr   = wid >> 1;     // 4 m-groups of 32
    const int wc   = wid & 1;      // 2 n-groups of 64
    const int m0   = blockIdx.y * 128;
    const int z    = blockIdx.z;
    const int sel  = (MODE == 0) ? (blockIdx.x >> 4) : 0;
    const int n0   = (MODE == 0) ? (blockIdx.x & 15) * 128 : blockIdx.x * 128;

    const __half* A;  int lda;
    const __half* Bm; int ldb;
    int Ktot;
    if (MODE == 0)      { A = g_xh;                  lda = EMB; Bm = g_wh[sel];              ldb = EMB; Ktot = EMB; }
    else if (MODE == 2) { A = g_sh + (size_t)z * SS; lda = SEQ; Bm = g_vth + (size_t)z * SD; ldb = SEQ; Ktot = m0 + 128; }
    else                { A = g_ctxh;                lda = EMB; Bm = g_wh[3];                ldb = EMB; Ktot = EMB; }
    const int T = Ktot / BK;

    const uint32_t sbase = smem_u32(dynh);

    // MODE2: per-thread softmax stats for the 4 fragment rows this thread owns
    float mst[4], rlst[4];
    int grow0 = 0;
    if (MODE == 2) {
        grow0 = m0 + wr * 32 + (lane >> 2);     // rows grow0 + {0,8,16,24}
        #pragma unroll
        for (int u = 0; u < 4; u++) {
            int r = grow0 + u * 8;
            mst[u]  = g_m[(size_t)z * SEQ + r];
            rlst[u] = 1.0f / g_l[(size_t)z * SEQ + r];
        }
    }

    auto load_stage = [&](int buf, int t) {
        const int k0 = t * BK;
        const uint32_t sa = sbase + (uint32_t)(buf * STAGE_H) * 2u;
        #pragma unroll
        for (int i = 0; i < 2; i++) {
            int id = tid + i * 256;
            int r = id >> 2, c8 = id & 3;
            cp16(sa + (uint32_t)(r * SA_H + c8 * 8) * 2u,
                 A + (size_t)(m0 + r) * lda + k0 + c8 * 8);
        }
        #pragma unroll
        for (int i = 0; i < 2; i++) {
            int id = tid + i * 256;
            int r = id >> 2, c8 = id & 3;
            cp16(sa + (uint32_t)(B_OFF_H + r * SA_H + c8 * 8) * 2u,
                 Bm + (size_t)(n0 + r) * ldb + k0 + c8 * 8);
        }
        asm volatile("cp.async.commit_group;\n");
    };

    float acc[2][8][4];
    #pragma unroll
    for (int i = 0; i < 2; i++)
        #pragma unroll
        for (int j = 0; j < 8; j++)
            #pragma unroll
            for (int e = 0; e < 4; e++) acc[i][j][e] = 0.0f;

    load_stage(0, 0);
    load_stage(1, 1);

    const int a_rsel = (lane & 7) + ((lane >> 3) & 1) * 8;
    const int a_ksel = ((lane >> 4) & 1) * 8;
    const int b_nsel = (lane & 7) + ((lane >> 4) & 1) * 8;
    const int b_ksel = ((lane >> 3) & 1) * 8;

    for (int t = 0; t < T; t++) {
        asm volatile("cp.async.wait_group 1;\n" ::: "memory");
        __syncthreads();

        if (t + 2 < T) load_stage((t + 2) % NSTAGE, t + 2);
        else asm volatile("cp.async.commit_group;\n");

        const uint32_t st = sbase + (uint32_t)((t % NSTAGE) * STAGE_H) * 2u;

        #pragma unroll
        for (int ks = 0; ks < 2; ks++) {     // two k16 steps per BK=32
            uint32_t a[2][4], b[8][2];
            #pragma unroll
            for (int i = 0; i < 2; i++)
                ldsm4(a[i], st + (uint32_t)((wr * 32 + i * 16 + a_rsel) * SA_H
                                            + ks * 16 + a_ksel) * 2u);
            #pragma unroll
            for (int u = 0; u < 4; u++) {
                uint32_t r[4];
                ldsm4(r, st + (uint32_t)(B_OFF_H + (wc * 64 + u * 16 + b_nsel) * SA_H
                                         + ks * 16 + b_ksel) * 2u);
                b[2 * u][0] = r[0]; b[2 * u][1] = r[1];
                b[2 * u + 1][0] = r[2]; b[2 * u + 1][1] = r[3];
            }
            if (MODE == 2) {   // fuse softmax exp + causal mask into A fragments
                const int kb = t * 32 + ks * 16 + (lane & 3) * 2;
                #pragma unroll
                for (int i = 0; i < 2; i++)
                    #pragma unroll
                    for (int e = 0; e < 4; e++) {
                        const int u  = i * 2 + (e & 1);
                        const int kg = kb + (e >> 1) * 8;
                        const int gr = grow0 + u * 8;
                        __half2 h2 = *reinterpret_cast<__half2*>(&a[i][e]);
                        float2 f = __half22float2(h2);
                        float p0 = (kg     <= gr) ? __expf((f.x - mst[u]) * INVSQ) * rlst[u] : 0.0f;
                        float p1 = (kg + 1 <= gr) ? __expf((f.y - mst[u]) * INVSQ) * rlst[u] : 0.0f;
                        __half2 r2 = __floats2half2_rn(p0, p1);
                        a[i][e] = *reinterpret_cast<uint32_t*>(&r2);
                    }
            }
            #pragma unroll
            for (int i = 0; i < 2; i++)
                #pragma unroll
                for (int j = 0; j < 8; j++)
                    mma_f16(acc[i][j], a[i], b[j]);
        }
    }

    // ---- epilogue ----
    const int er = lane >> 2;
    const int ec = (lane & 3) * 2;

    if (MODE == 3) {
        float* base = Oext + (size_t)m0 * EMB + n0;
        #pragma unroll
        for (int i = 0; i < 2; i++)
            #pragma unroll
            for (int j = 0; j < 8; j++) {
                int lrow = wr * 32 + i * 16 + er;
                int lcol = wc * 64 + j * 8 + ec;
                float b0 = bias[n0 + lcol], b1 = bias[n0 + lcol + 1];
                *(float2*)(base + (size_t)lrow * EMB + lcol) =
                    make_float2(acc[i][j][0] + b0, acc[i][j][1] + b1);
                *(float2*)(base + (size_t)(lrow + 8) * EMB + lcol) =
                    make_float2(acc[i][j][2] + b0, acc[i][j][3] + b1);
            }
    } else {
        __half* hb; size_t ldo;
        if (MODE == 0) {
            int b = m0 >> 11;
            __half* qkv = (sel == 0 ? g_qh : sel == 1 ? g_kh : g_vh);
            hb = qkv + ((size_t)(b * NH + (blockIdx.x & 15))) * SD + (size_t)(m0 & (SEQ - 1)) * DH;
            ldo = DH;
        } else {
            int b = z >> 4, h = z & 15;
            hb = g_ctxh + (size_t)b * SEQ * EMB + (size_t)m0 * EMB + h * DH;
            ldo = EMB;
        }
        #pragma unroll
        for (int i = 0; i < 2; i++)
            #pragma unroll
            for (int j = 0; j < 8; j++) {
                int lrow = wr * 32 + i * 16 + er;
                int lcol = wc * 64 + j * 8 + ec;
                *(__half2*)(hb + (size_t)lrow * ldo + lcol) =
                    __floats2half2_rn(acc[i][j][0], acc[i][j][1]);
                *(__half2*)(hb + (size_t)(lrow + 8) * ldo + lcol) =
                    __floats2half2_rn(acc[i][j][2], acc[i][j][3]);
            }
    }
}

// ---------------------------------------------------------------------------
// scores = Q K^T row-panel: one CTA per (q-panel, bh). Q panel (128x128 fp16)
// smem-resident; K chunks streamed in a 3-slot ring across bx = 0..by.
// Per-n-tile epilogue: fp16 S store + per-block softmax partials.
// by = 15 - blockIdx.x (big panels first for load balance).
// ---------------------------------------------------------------------------
#define RP_CHUNK (128 * SA_H)                   // halves per 32-k A chunk (5120)
#define RP_PANEL (4 * RP_CHUNK)                 // 20480 halves = 40960 B
#define RP_BSLOT (128 * SA_H)                   // 5120 halves = 10240 B
#define RP_STAT  (RP_PANEL + 3 * RP_BSLOT)      // halves offset of float scratch
#define RP_SMEM  (RP_STAT * 2 + 512 * 4)        // 73728 B

__global__ __launch_bounds__(256, 2)
void scores_rowpanel()
{
    extern __shared__ __align__(16) char dynRaw[];
    __half* dynh = (__half*)dynRaw;
    float* sm_m = (float*)(dynh + RP_STAT);        // [8][32]
    float* sm_l = sm_m + 256;

    const int tid  = threadIdx.x;
    const int wid  = tid >> 5;
    const int lane = tid & 31;
    const int wr   = wid >> 1;
    const int wc   = wid & 1;
    const int by   = 15 - blockIdx.x;
    const int z    = blockIdx.y;
    const int m0   = by * 128;

    const __half* A = g_qh + (size_t)z * SD;
    const __half* B = g_kh + (size_t)z * SD;
    const uint32_t sbase = smem_u32(dynh);

    // Q panel: 128 rows x 128 halves = 2048 16B chunks, 8/thread
    #pragma unroll
    for (int i = 0; i < 8; i++) {
        int id = tid + i * 256;
        int r = id >> 4, c8 = id & 15;          // c8: 16B chunk within row
        int kc = c8 >> 2, cc = c8 & 3;
        cp16(sbase + (uint32_t)(kc * RP_CHUNK + r * SA_H + cc * 8) * 2u,
             A + (size_t)(m0 + r) * DH + c8 * 8);
    }
    asm volatile("cp.async.commit_group;\n");

    const int S = 4 * (by + 1);

    auto load_b = [&](int s) {
        int bx = s >> 2, kc = s & 3;
        uint32_t sb = sbase + (uint32_t)(RP_PANEL + (s % 3) * RP_BSLOT) * 2u;
        #pragma unroll
        for (int i = 0; i < 2; i++) {
            int id = tid + i * 256;
            int r = id >> 2, c8 = id & 3;
            cp16(sb + (uint32_t)(r * SA_H + c8 * 8) * 2u,
                 B + (size_t)(bx * 128 + r) * DH + kc * 32 + c8 * 8);
        }
        asm volatile("cp.async.commit_group;\n");
    };

    load_b(0);
    load_b(1);

    float acc[2][8][4];
    #pragma unroll
    for (int i = 0; i < 2; i++)
        #pragma unroll
        for (int j = 0; j < 8; j++)
            #pragma unroll
            for (int e = 0; e < 4; e++) acc[i][j][e] = 0.0f;

    const int a_rsel = (lane & 7) + ((lane >> 3) & 1) * 8;
    const int a_ksel = ((lane >> 4) & 1) * 8;
    const int b_nsel = (lane & 7) + ((lane >> 4) & 1) * 8;
    const int b_ksel = ((lane >> 3) & 1) * 8;
    const int er = lane >> 2;
    const int ec = (lane & 3) * 2;

    for (int s = 0; s < S; s++) {
        asm volatile("cp.async.wait_group 1;\n" ::: "memory");
        __syncthreads();

        if (s + 2 < S) load_b(s + 2);
        else asm volatile("cp.async.commit_group;\n");

        const int kc = s & 3;
        const uint32_t sa = sbase + (uint32_t)(kc * RP_CHUNK) * 2u;
        const uint32_t sb = sbase + (uint32_t)(RP_PANEL + (s % 3) * RP_BSLOT) * 2u;

        #pragma unroll
        for (int ks = 0; ks < 2; ks++) {
            uint32_t a[2][4], b[8][2];
            #pragma unroll
            for (int i = 0; i < 2; i++)
                ldsm4(a[i], sa + (uint32_t)((wr * 32 + i * 16 + a_rsel) * SA_H
                                            + ks * 16 + a_ksel) * 2u);
            #pragma unroll
            for (int u = 0; u < 4; u++) {
                uint32_t r[4];
                ldsm4(r, sb + (uint32_t)((wc * 64 + u * 16 + b_nsel) * SA_H
                                         + ks * 16 + b_ksel) * 2u);
                b[2 * u][0] = r[0]; b[2 * u][1] = r[1];
                b[2 * u + 1][0] = r[2]; b[2 * u + 1][1] = r[3];
            }
            #pragma unroll
            for (int i = 0; i < 2; i++)
                #pragma unroll
                for (int j = 0; j < 8; j++)
                    mma_f16(acc[i][j], a[i], b[j]);
        }

        if ((s & 3) == 3) {     // n-tile bx done: store S + partials, rezero
            const int bx = s >> 2;
            const int n0 = bx * 128;
            __half* hb = g_sh + (size_t)z * SS + (size_t)m0 * SEQ + n0;

            #pragma unroll
            for (int i = 0; i < 2; i++)
                #pragma unroll
                for (int j = 0; j < 8; j++) {
                    int lrow = wr * 32 + i * 16 + er;
                    int lcol = wc * 64 + j * 8 + ec;
                    *(__half2*)(hb + (size_t)lrow * SEQ + lcol) =
                        __floats2half2_rn(acc[i][j][0], acc[i][j][1]);
                    *(__half2*)(hb + (size_t)(lrow + 8) * SEQ + lcol) =
                        __floats2half2_rn(acc[i][j][2], acc[i][j][3]);
                }

            // per-block softmax partials from fp32 registers
            #pragma unroll
            for (int i = 0; i < 2; i++)
                #pragma unroll
                for (int h = 0; h < 2; h++) {
                    const int lrow = wr * 32 + i * 16 + er + h * 8;
                    const int grow = m0 + lrow;
                    float mx = -1e30f;
                    #pragma unroll
                    for (int j = 0; j < 8; j++) {
                        int c0 = n0 + wc * 64 + j * 8 + ec;
                        float x0 = (c0     <= grow) ? acc[i][j][h * 2]     : -1e30f;
                        float x1 = (c0 + 1 <= grow) ? acc[i][j][h * 2 + 1] : -1e30f;
                        mx = fmaxf(mx, fmaxf(x0, x1));
                    }
                    mx = fmaxf(mx, __shfl_xor_sync(0xFFFFFFFFu, mx, 1));
                    mx = fmaxf(mx, __shfl_xor_sync(0xFFFFFFFFu, mx, 2));
                    float sum = 0.0f;
                    #pragma unroll
                    for (int j = 0; j < 8; j++) {
                        int c0 = n0 + wc * 64 + j * 8 + ec;
                        if (c0     <= grow) sum += __expf((acc[i][j][h * 2]     - mx) * INVSQ);
                        if (c0 + 1 <= grow) sum += __expf((acc[i][j][h * 2 + 1] - mx) * INVSQ);
                    }
                    sum += __shfl_xor_sync(0xFFFFFFFFu, sum, 1);
                    sum += __shfl_xor_sync(0xFFFFFFFFu, sum, 2);
                    if ((lane & 3) == 0) {
                        int rl32 = i * 16 + er + h * 8;
                        sm_m[wid * 32 + rl32] = mx;
                        sm_l[wid * 32 + rl32] = sum;
                    }
                    #pragma unroll
                    for (int j = 0; j < 8; j++) {
                        acc[i][j][h * 2] = 0.0f; acc[i][j][h * 2 + 1] = 0.0f;
                    }
                }
            __syncthreads();
            if (tid < 128) {
                int r = tid, wrg = r >> 5, rl32 = r & 31;
                float ma = sm_m[(wrg * 2) * 32 + rl32];
                float mb = sm_m[(wrg * 2 + 1) * 32 + rl32];
                float mm = fmaxf(ma, mb);
                float ll = __expf((ma - mm) * INVSQ) * sm_l[(wrg * 2) * 32 + rl32]
                         + __expf((mb - mm) * INVSQ) * sm_l[(wrg * 2 + 1) * 32 + rl32];
                size_t off = ((size_t)z * 16 + bx) * SEQ + m0 + r;
                g_pm[off] = mm;
                g_pl[off] = ll;
            }
        }
    }
}

// ---------------------------------------------------------------------------
// combine per-block partials into per-row softmax stats (m, l)
// ---------------------------------------------------------------------------
__global__ __launch_bounds__(256)
void combine_stats()
{
    int idx = blockIdx.x * 256 + threadIdx.x;   // 0 .. BH*SEQ-1
    int z = idx >> 11;
    int q = idx & (SEQ - 1);
    int nb = (q >> 7) + 1;

    float m = -1e30f;
    for (int b = 0; b < nb; b++)
        m = fmaxf(m, g_pm[((size_t)z * 16 + b) * SEQ + q]);
    float l = 0.0f;
    for (int b = 0; b < nb; b++) {
        size_t off = ((size_t)z * 16 + b) * SEQ + q;
        l += __expf((g_pm[off] - m) * INVSQ) * g_pl[off];
    }
    g_m[(size_t)z * SEQ + q] = m;
    g_l[(size_t)z * SEQ + q] = l;
}

// ---------------------------------------------------------------------------
// convert inputs to fp16: x -> g_xh, Wq/Wk/Wv/Wo -> g_wh[0..3]
// ---------------------------------------------------------------------------
__global__ __launch_bounds__(256)
void cvt_inputs(const float4* __restrict__ x,  const float4* __restrict__ wq,
                const float4* __restrict__ wk, const float4* __restrict__ wv,
                const float4* __restrict__ wo)
{
    const int XC = BATCH * SEQ * EMB / 4;
    const int WC = EMB * EMB / 4;
    int i = blockIdx.x * 256 + threadIdx.x;
    float4 v; __half* dst;
    if (i < XC) { v = x[i]; dst = g_xh + (size_t)i * 4; }
    else {
        int r = i - XC;
        int s = r / WC, o = r - s * WC;
        const float4* w = (s == 0 ? wq : s == 1 ? wk : s == 2 ? wv : wo);
        v = w[o]; dst = g_wh[s] + (size_t)o * 4;
    }
    *(__half2*)dst       = __floats2half2_rn(v.x, v.y);
    *(__half2*)(dst + 2) = __floats2half2_rn(v.z, v.w);
}

// ---------------------------------------------------------------------------
// V transpose: g_vh [bh][k][dh] -> g_vth [bh][dh][k], fp16 32x32 tiles
// ---------------------------------------------------------------------------
__global__ __launch_bounds__(256)
void transpose_v()
{
    __shared__ __half tile[32][33];
    const int z  = blockIdx.z;
    const int k0 = blockIdx.x * 32;
    const int n0 = blockIdx.y * 32;
    const int tx = threadIdx.x & 31;
    const int ty = threadIdx.x >> 5;

    const __half* src = g_vh + (size_t)z * SD;
    #pragma unroll
    for (int j = 0; j < 4; j++)
        tile[ty + j * 8][tx] = src[(size_t)(k0 + ty + j * 8) * DH + n0 + tx];
    __syncthreads();
    __half* dst = g_vth + (size_t)z * SD;
    #pragma unroll
    for (int j = 0; j < 4; j++)
        dst[(size_t)(n0 + ty + j * 8) * SEQ + k0 + tx] = tile[tx][ty + j * 8];
}

extern "C" void kernel_launch(void* const* d_in, const int* in_sizes, int n_in,
                              void* d_out, int out_size)
{
    const float* x  = (const float*)d_in[0];
    const float* Wq = (const float*)d_in[1];
    const float* Wk = (const float*)d_in[2];
    const float* Wv = (const float*)d_in[3];
    const float* Wo = (const float*)d_in[4];
    const float* bo = (const float*)d_in[5];
    float* out = (float*)d_out;

    cudaFuncSetAttribute(gemm_tc<0>, cudaFuncAttributeMaxDynamicSharedMemorySize, SMEM_BYTES);
    cudaFuncSetAttribute(gemm_tc<2>, cudaFuncAttributeMaxDynamicSharedMemorySize, SMEM_BYTES);
    cudaFuncSetAttribute(gemm_tc<3>, cudaFuncAttributeMaxDynamicSharedMemorySize, SMEM_BYTES);
    cudaFuncSetAttribute(scores_rowpanel, cudaFuncAttributeMaxDynamicSharedMemorySize, RP_SMEM);

    dim3 blk(256);
    const int XC = BATCH * SEQ * EMB / 4;
    const int WC = EMB * EMB / 4;

    // fp32 -> fp16 inputs
    cvt_inputs<<<(XC + 4 * WC) / 256, blk>>>((const float4*)x, (const float4*)Wq,
                                             (const float4*)Wk, (const float4*)Wv,
                                             (const float4*)Wo);

    // fused QKV: grid.x = 48 (3 weights x 16 head tiles)
    gemm_tc<0><<<dim3(48, 64, 1), blk, SMEM_BYTES>>>(nullptr, nullptr);

    // V transpose for MODE2's B operand
    transpose_v<<<dim3(SEQ / 32, DH / 32, BH), blk>>>();

    // scores = Q K^T row-panel + in-epilogue softmax partials
    scores_rowpanel<<<dim3(16, BH), blk, RP_SMEM>>>();

    // combine partials -> per-row (m, l)
    combine_stats<<<BH * SEQ / 256, 256>>>();

    // ctx = softmax(S) V per (b,h); exp fused into A fragments
    gemm_tc<2><<<dim3(1, 16, BH), blk, SMEM_BYTES>>>(nullptr, nullptr);

    // out = ctx Wo^T + bias (fp32 out)
    gemm_tc<3><<<dim3(16, 64, 1), blk, SMEM_BYTES>>>(out, bo);
}

// round 15
// speedup vs baseline: 1.1017x; 1.1017x over previous
#include <cuda_runtime.h>
#include <cuda_fp16.h>
#include <cstdint>

// ---------------- problem constants ----------------
#define BATCH 4
#define SEQ 2048
#define EMB 2048
#define NH 16
#define DH 128
#define BH (BATCH * NH)          // 64
#define SD (SEQ * DH)            // 262144
#define SS ((size_t)SEQ * SEQ)
#define INVSQ 0.08838834764831845f   // 1/sqrt(128)

// scratch (allocation-free rule) — all fp16 except stats
__device__ __half g_xh[(size_t)BATCH * SEQ * EMB];
__device__ __half g_wh[4][(size_t)EMB * EMB];
__device__ __half g_qh[(size_t)BH * SD];
__device__ __half g_kh[(size_t)BH * SD];
__device__ __half g_vh[(size_t)BH * SD];
__device__ __half g_vth[(size_t)BH * SD];           // V transposed: [bh][dh][seq]
__device__ __half g_sh[(size_t)BH * SS];            // raw scores
__device__ __half g_ctxh[(size_t)BATCH * SEQ * EMB];
__device__ float g_m[(size_t)BH * SEQ];
__device__ float g_l[(size_t)BH * SEQ];
__device__ float g_pm[(size_t)BH * 16 * SEQ];
__device__ float g_pl[(size_t)BH * 16 * SEQ];

__device__ __forceinline__ uint32_t smem_u32(const void* p) {
    return (uint32_t)__cvta_generic_to_shared(p);
}
__device__ __forceinline__ void cp16(uint32_t s, const void* g) {
    asm volatile("cp.async.cg.shared.global [%0], [%1], 16;\n" :: "r"(s), "l"(g));
}
__device__ __forceinline__ void ldsm4(uint32_t* r, uint32_t addr) {
    asm volatile("ldmatrix.sync.aligned.m8n8.x4.shared.b16 {%0,%1,%2,%3}, [%4];"
                 : "=r"(r[0]), "=r"(r[1]), "=r"(r[2]), "=r"(r[3]) : "r"(addr));
}
__device__ __forceinline__ void mma_f16(float* c, const uint32_t* a, const uint32_t* b) {
    asm volatile(
        "mma.sync.aligned.m16n8k16.row.col.f32.f16.f16.f32 "
        "{%0,%1,%2,%3},{%4,%5,%6,%7},{%8,%9},{%0,%1,%2,%3};"
        : "+f"(c[0]), "+f"(c[1]), "+f"(c[2]), "+f"(c[3])
        : "r"(a[0]), "r"(a[1]), "r"(a[2]), "r"(a[3]), "r"(b[0]), "r"(b[1]));
}

// ---------------------------------------------------------------------------
// FP16 mma.sync GEMM (fp32 accum), CTA 128x128, 256 threads = 8 warps (4m x 2n),
// warp tile 32x64, BK=64, 3-stage cp.async pipeline, ldmatrix operands.
// Smem tiles fp16 K-contiguous [row][k], stride 72 halves (144B, conflict-free).
// MODE 0: fused QKV proj; grid.x=48: sel=bx>>4 picks Wq/Wk/Wv, head=bx&15.
// MODE 1: scores = Q K^T per (b,h), fp16 out + per-block softmax partials
//         in epilogue; above-diagonal blocks skipped.
// MODE 2: ctx = softmax(S) V per (b,h); exp+mask fused into A fragments,
//         B = pre-transposed g_vth, K truncated causally.
// MODE 3: out proj C = ctx * Wo^T + bias, fp32 out.
// ---------------------------------------------------------------------------
#define BK 64
#define SA_H 72                                 // tile row stride (halves)
#define B_OFF_H (128 * SA_H)                    // halves
#define STAGE_H (2 * 128 * SA_H)                // 18432 halves = 36864 B
#define NSTAGE 3
#define SMEM_BYTES (NSTAGE * STAGE_H * 2)       // 110592

template<int MODE>
__global__ __launch_bounds__(256, 2)
void gemm_tc(float* __restrict__ Oext, const float* __restrict__ bias)
{
    if (MODE == 1 && blockIdx.x > blockIdx.y) return;   // fully-masked causal block

    extern __shared__ __align__(16) char dynRaw[];
    __half* dynh = (__half*)dynRaw;

    const int tid  = threadIdx.x;
    const int wid  = tid >> 5;
    const int lane = tid & 31;
    const int wr   = wid >> 1;     // 4 m-groups of 32
    const int wc   = wid & 1;      // 2 n-groups of 64
    const int m0   = blockIdx.y * 128;
    const int z    = blockIdx.z;
    const int sel  = (MODE == 0) ? (blockIdx.x >> 4) : 0;
    const int n0   = (MODE == 0) ? (blockIdx.x & 15) * 128 : blockIdx.x * 128;

    const __half* A;  int lda;
    const __half* Bm; int ldb;
    int Ktot;
    if (MODE == 0)      { A = g_xh;                  lda = EMB; Bm = g_wh[sel];              ldb = EMB; Ktot = EMB; }
    else if (MODE == 1) { A = g_qh + (size_t)z * SD; lda = DH;  Bm = g_kh + (size_t)z * SD;  ldb = DH;  Ktot = DH; }
    else if (MODE == 2) { A = g_sh + (size_t)z * SS; lda = SEQ; Bm = g_vth + (size_t)z * SD; ldb = SEQ; Ktot = m0 + 128; }
    else                { A = g_ctxh;                lda = EMB; Bm = g_wh[3];                ldb = EMB; Ktot = EMB; }
    const int T = Ktot / BK;

    const uint32_t sbase = smem_u32(dynh);

    // MODE2: per-thread softmax stats for the 4 fragment rows this thread owns
    float mst[4], rlst[4];
    int grow0 = 0;
    if (MODE == 2) {
        grow0 = m0 + wr * 32 + (lane >> 2);     // rows grow0 + {0,8,16,24}
        #pragma unroll
        for (int u = 0; u < 4; u++) {
            int r = grow0 + u * 8;
            mst[u]  = g_m[(size_t)z * SEQ + r];
            rlst[u] = 1.0f / g_l[(size_t)z * SEQ + r];
        }
    }

    auto load_stage = [&](int buf, int t) {
        const int k0 = t * BK;
        const uint32_t sa = sbase + (uint32_t)(buf * STAGE_H) * 2u;
        // A: 128 rows x 64 halves = 1024 16B chunks, 4/thread
        #pragma unroll
        for (int i = 0; i < 4; i++) {
            int id = tid + i * 256;
            int r = id >> 3, c8 = id & 7;
            cp16(sa + (uint32_t)(r * SA_H + c8 * 8) * 2u,
                 A + (size_t)(m0 + r) * lda + k0 + c8 * 8);
        }
        // B: rows are N-dim, K contiguous
        #pragma unroll
        for (int i = 0; i < 4; i++) {
            int id = tid + i * 256;
            int r = id >> 3, c8 = id & 7;
            cp16(sa + (uint32_t)(B_OFF_H + r * SA_H + c8 * 8) * 2u,
                 Bm + (size_t)(n0 + r) * ldb + k0 + c8 * 8);
        }
        asm volatile("cp.async.commit_group;\n");
    };

    float acc[2][8][4];
    #pragma unroll
    for (int i = 0; i < 2; i++)
        #pragma unroll
        for (int j = 0; j < 8; j++)
            #pragma unroll
            for (int e = 0; e < 4; e++) acc[i][j][e] = 0.0f;

    load_stage(0, 0);
    load_stage(1, 1);

    // ldmatrix addressing (halves)
    const int a_rsel = (lane & 7) + ((lane >> 3) & 1) * 8;
    const int a_ksel = ((lane >> 4) & 1) * 8;
    const int b_nsel = (lane & 7) + ((lane >> 4) & 1) * 8;
    const int b_ksel = ((lane >> 3) & 1) * 8;

    for (int t = 0; t < T; t++) {
        asm volatile("cp.async.wait_group 1;\n" ::: "memory");
        __syncthreads();

        if (t + 2 < T) load_stage((t + 2) % NSTAGE, t + 2);
        else asm volatile("cp.async.commit_group;\n");

        const uint32_t st = sbase + (uint32_t)((t % NSTAGE) * STAGE_H) * 2u;

        #pragma unroll
        for (int ks = 0; ks < 4; ks++) {     // four k16 steps per BK=64
            uint32_t a[2][4], b[8][2];
            #pragma unroll
            for (int i = 0; i < 2; i++)
                ldsm4(a[i], st + (uint32_t)((wr * 32 + i * 16 + a_rsel) * SA_H
                                            + ks * 16 + a_ksel) * 2u);
            #pragma unroll
            for (int u = 0; u < 4; u++) {
                uint32_t r[4];
                ldsm4(r, st + (uint32_t)(B_OFF_H + (wc * 64 + u * 16 + b_nsel) * SA_H
                                         + ks * 16 + b_ksel) * 2u);
                b[2 * u][0] = r[0]; b[2 * u][1] = r[1];
                b[2 * u + 1][0] = r[2]; b[2 * u + 1][1] = r[3];
            }
            if (MODE == 2) {   // fuse softmax exp + causal mask into A fragments
                const int kb = t * BK + ks * 16 + (lane & 3) * 2;
                #pragma unroll
                for (int i = 0; i < 2; i++)
                    #pragma unroll
                    for (int e = 0; e < 4; e++) {
                        const int u  = i * 2 + (e & 1);
                        const int kg = kb + (e >> 1) * 8;
                        const int gr = grow0 + u * 8;
                        __half2 h2 = *reinterpret_cast<__half2*>(&a[i][e]);
                        float2 f = __half22float2(h2);
                        float p0 = (kg     <= gr) ? __expf((f.x - mst[u]) * INVSQ) * rlst[u] : 0.0f;
                        float p1 = (kg + 1 <= gr) ? __expf((f.y - mst[u]) * INVSQ) * rlst[u] : 0.0f;
                        __half2 r2 = __floats2half2_rn(p0, p1);
                        a[i][e] = *reinterpret_cast<uint32_t*>(&r2);
                    }
            }
            #pragma unroll
            for (int i = 0; i < 2; i++)
                #pragma unroll
                for (int j = 0; j < 8; j++)
                    mma_f16(acc[i][j], a[i], b[j]);
        }
    }

    // ---- epilogue ----
    const int er = lane >> 2;
    const int ec = (lane & 3) * 2;

    if (MODE == 3) {
        float* base = Oext + (size_t)m0 * EMB + n0;
        #pragma unroll
        for (int i = 0; i < 2; i++)
            #pragma unroll
            for (int j = 0; j < 8; j++) {
                int lrow = wr * 32 + i * 16 + er;
                int lcol = wc * 64 + j * 8 + ec;
                float b0 = bias[n0 + lcol], b1 = bias[n0 + lcol + 1];
                *(float2*)(base + (size_t)lrow * EMB + lcol) =
                    make_float2(acc[i][j][0] + b0, acc[i][j][1] + b1);
                *(float2*)(base + (size_t)(lrow + 8) * EMB + lcol) =
                    make_float2(acc[i][j][2] + b0, acc[i][j][3] + b1);
            }
    } else {
        __half* hb; size_t ldo;
        if (MODE == 0) {
            int b = m0 >> 11;
            __half* qkv = (sel == 0 ? g_qh : sel == 1 ? g_kh : g_vh);
            hb = qkv + ((size_t)(b * NH + (blockIdx.x & 15))) * SD + (size_t)(m0 & (SEQ - 1)) * DH;
            ldo = DH;
        } else if (MODE == 1) {
            hb = g_sh + (size_t)z * SS + (size_t)m0 * SEQ + n0;
            ldo = SEQ;
        } else {
            int b = z >> 4, h = z & 15;
            hb = g_ctxh + (size_t)b * SEQ * EMB + (size_t)m0 * EMB + h * DH;
            ldo = EMB;
        }
        #pragma unroll
        for (int i = 0; i < 2; i++)
            #pragma unroll
            for (int j = 0; j < 8; j++) {
                int lrow = wr * 32 + i * 16 + er;
                int lcol = wc * 64 + j * 8 + ec;
                *(__half2*)(hb + (size_t)lrow * ldo + lcol) =
                    __floats2half2_rn(acc[i][j][0], acc[i][j][1]);
                *(__half2*)(hb + (size_t)(lrow + 8) * ldo + lcol) =
                    __floats2half2_rn(acc[i][j][2], acc[i][j][3]);
            }
    }

    // ---- MODE1: per-block softmax partials (pm, pl) from fp32 registers ----
    if (MODE == 1) {
        __syncthreads();                         // pipeline smem dead; reuse
        float* sm_m = (float*)dynRaw;            // [8 warps][32 rows]
        float* sm_l = (float*)dynRaw + 256;

        #pragma unroll
        for (int i = 0; i < 2; i++)
            #pragma unroll
            for (int h = 0; h < 2; h++) {
                const int lrow = wr * 32 + i * 16 + er + h * 8;
                const int grow = m0 + lrow;
                float mx = -1e30f;
                #pragma unroll
                for (int j = 0; j < 8; j++) {
                    int c0 = n0 + wc * 64 + j * 8 + ec;
                    float x0 = (c0     <= grow) ? acc[i][j][h * 2]     : -1e30f;
                    float x1 = (c0 + 1 <= grow) ? acc[i][j][h * 2 + 1] : -1e30f;
                    mx = fmaxf(mx, fmaxf(x0, x1));
                }
                mx = fmaxf(mx, __shfl_xor_sync(0xFFFFFFFFu, mx, 1));
                mx = fmaxf(mx, __shfl_xor_sync(0xFFFFFFFFu, mx, 2));
                float sum = 0.0f;
                #pragma unroll
                for (int j = 0; j < 8; j++) {
                    int c0 = n0 + wc * 64 + j * 8 + ec;
                    if (c0     <= grow) sum += __expf((acc[i][j][h * 2]     - mx) * INVSQ);
                    if (c0 + 1 <= grow) sum += __expf((acc[i][j][h * 2 + 1] - mx) * INVSQ);
                }
                sum += __shfl_xor_sync(0xFFFFFFFFu, sum, 1);
                sum += __shfl_xor_sync(0xFFFFFFFFu, sum, 2);
                if ((lane & 3) == 0) {
                    int rl32 = i * 16 + er + h * 8;
                    sm_m[wid * 32 + rl32] = mx;
                    sm_l[wid * 32 + rl32] = sum;
                }
            }
        __syncthreads();
        if (tid < 128) {
            int r = tid, wrg = r >> 5, rl32 = r & 31;
            float ma = sm_m[(wrg * 2) * 32 + rl32];
            float mb = sm_m[(wrg * 2 + 1) * 32 + rl32];
            float mm = fmaxf(ma, mb);
            float ll = __expf((ma - mm) * INVSQ) * sm_l[(wrg * 2) * 32 + rl32]
                     + __expf((mb - mm) * INVSQ) * sm_l[(wrg * 2 + 1) * 32 + rl32];
            size_t off = ((size_t)z * 16 + blockIdx.x) * SEQ + m0 + r;
            g_pm[off] = mm;
            g_pl[off] = ll;
        }
    }
}

// ---------------------------------------------------------------------------
// combine per-block partials into per-row softmax stats (m, l)
// ---------------------------------------------------------------------------
__global__ __launch_bounds__(256)
void combine_stats()
{
    int idx = blockIdx.x * 256 + threadIdx.x;   // 0 .. BH*SEQ-1
    int z = idx >> 11;
    int q = idx & (SEQ - 1);
    int nb = (q >> 7) + 1;

    float m = -1e30f;
    for (int b = 0; b < nb; b++)
        m = fmaxf(m, g_pm[((size_t)z * 16 + b) * SEQ + q]);
    float l = 0.0f;
    for (int b = 0; b < nb; b++) {
        size_t off = ((size_t)z * 16 + b) * SEQ + q;
        l += __expf((g_pm[off] - m) * INVSQ) * g_pl[off];
    }
    g_m[(size_t)z * SEQ + q] = m;
    g_l[(size_t)z * SEQ + q] = l;
}

// ---------------------------------------------------------------------------
// convert inputs to fp16: x -> g_xh, Wq/Wk/Wv/Wo -> g_wh[0..3]
// ---------------------------------------------------------------------------
__global__ __launch_bounds__(256)
void cvt_inputs(const float4* __restrict__ x,  const float4* __restrict__ wq,
                const float4* __restrict__ wk, const float4* __restrict__ wv,
                const float4* __restrict__ wo)
{
    const int XC = BATCH * SEQ * EMB / 4;
    const int WC = EMB * EMB / 4;
    int i = blockIdx.x * 256 + threadIdx.x;
    float4 v; __half* dst;
    if (i < XC) { v = x[i]; dst = g_xh + (size_t)i * 4; }
    else {
        int r = i - XC;
        int s = r / WC, o = r - s * WC;
        const float4* w = (s == 0 ? wq : s == 1 ? wk : s == 2 ? wv : wo);
        v = w[o]; dst = g_wh[s] + (size_t)o * 4;
    }
    *(__half2*)dst       = __floats2half2_rn(v.x, v.y);
    *(__half2*)(dst + 2) = __floats2half2_rn(v.z, v.w);
}

// ---------------------------------------------------------------------------
// V transpose: g_vh [bh][k][dh] -> g_vth [bh][dh][k], fp16 32x32 tiles
// ---------------------------------------------------------------------------
__global__ __launch_bounds__(256)
void transpose_v()
{
    __shared__ __half tile[32][33];
    const int z  = blockIdx.z;
    const int k0 = blockIdx.x * 32;
    const int n0 = blockIdx.y * 32;
    const int tx = threadIdx.x & 31;
    const int ty = threadIdx.x >> 5;

    const __half* src = g_vh + (size_t)z * SD;
    #pragma unroll
    for (int j = 0; j < 4; j++)
        tile[ty + j * 8][tx] = src[(size_t)(k0 + ty + j * 8) * DH + n0 + tx];
    __syncthreads();
    __half* dst = g_vth + (size_t)z * SD;
    #pragma unroll
    for (int j = 0; j < 4; j++)
        dst[(size_t)(n0 + ty + j * 8) * SEQ + k0 + tx] = tile[tx][ty + j * 8];
}

extern "C" void kernel_launch(void* const* d_in, const int* in_sizes, int n_in,
                              void* d_out, int out_size)
{
    const float* x  = (const float*)d_in[0];
    const float* Wq = (const float*)d_in[1];
    const float* Wk = (const float*)d_in[2];
    const float* Wv = (const float*)d_in[3];
    const float* Wo = (const float*)d_in[4];
    const float* bo = (const float*)d_in[5];
    float* out = (float*)d_out;

    cudaFuncSetAttribute(gemm_tc<0>, cudaFuncAttributeMaxDynamicSharedMemorySize, SMEM_BYTES);
    cudaFuncSetAttribute(gemm_tc<1>, cudaFuncAttributeMaxDynamicSharedMemorySize, SMEM_BYTES);
    cudaFuncSetAttribute(gemm_tc<2>, cudaFuncAttributeMaxDynamicSharedMemorySize, SMEM_BYTES);
    cudaFuncSetAttribute(gemm_tc<3>, cudaFuncAttributeMaxDynamicSharedMemorySize, SMEM_BYTES);

    dim3 blk(256);
    const int XC = BATCH * SEQ * EMB / 4;
    const int WC = EMB * EMB / 4;

    // fp32 -> fp16 inputs
    cvt_inputs<<<(XC + 4 * WC) / 256, blk>>>((const float4*)x, (const float4*)Wq,
                                             (const float4*)Wk, (const float4*)Wv,
                                             (const float4*)Wo);

    // fused QKV: grid.x = 48 (3 weights x 16 head tiles)
    gemm_tc<0><<<dim3(48, 64, 1), blk, SMEM_BYTES>>>(nullptr, nullptr);

    // V transpose for MODE2's B operand
    transpose_v<<<dim3(SEQ / 32, DH / 32, BH), blk>>>();

    // scores = Q K^T per (b,h) + in-epilogue softmax partials
    gemm_tc<1><<<dim3(16, 16, BH), blk, SMEM_BYTES>>>(nullptr, nullptr);

    // combine partials -> per-row (m, l)
    combine_stats<<<BH * SEQ / 256, 256>>>();

    // ctx = softmax(S) V per (b,h); exp fused into A fragments
    gemm_tc<2><<<dim3(1, 16, BH), blk, SMEM_BYTES>>>(nullptr, nullptr);

    // out = ctx Wo^T + bias (fp32 out)
    gemm_tc<3><<<dim3(16, 64, 1), blk, SMEM_BYTES>>>(out, bo);
}

// round 16
// speedup vs baseline: 1.3450x; 1.2208x over previous
#include <cuda_runtime.h>
#include <cuda_fp16.h>
#include <cstdint>

// ---------------- problem constants ----------------
#define BATCH 4
#define SEQ 2048
#define EMB 2048
#define NH 16
#define DH 128
#define BH (BATCH * NH)          // 64
#define SD (SEQ * DH)            // 262144
#define SS ((size_t)SEQ * SEQ)
#define INVSQ 0.08838834764831845f   // 1/sqrt(128)

// scratch (allocation-free rule)
__device__ __half g_xh[(size_t)BATCH * SEQ * EMB];
__device__ __half g_wh[4][(size_t)EMB * EMB];
__device__ __half g_qh[(size_t)BH * SD];
__device__ __half g_kh[(size_t)BH * SD];
__device__ __half g_vh[(size_t)BH * SD];
__device__ __half g_vth[(size_t)BH * SD];           // V transposed: [bh][dh][seq]
__device__ __half g_ctxh[(size_t)BATCH * SEQ * EMB];

__device__ __forceinline__ uint32_t smem_u32(const void* p) {
    return (uint32_t)__cvta_generic_to_shared(p);
}
__device__ __forceinline__ void cp16(uint32_t s, const void* g) {
    asm volatile("cp.async.cg.shared.global [%0], [%1], 16;\n" :: "r"(s), "l"(g));
}
__device__ __forceinline__ void ldsm4(uint32_t* r, uint32_t addr) {
    asm volatile("ldmatrix.sync.aligned.m8n8.x4.shared.b16 {%0,%1,%2,%3}, [%4];"
                 : "=r"(r[0]), "=r"(r[1]), "=r"(r[2]), "=r"(r[3]) : "r"(addr));
}
__device__ __forceinline__ void mma_f16(float* c, const uint32_t* a, const uint32_t* b) {
    asm volatile(
        "mma.sync.aligned.m16n8k16.row.col.f32.f16.f16.f32 "
        "{%0,%1,%2,%3},{%4,%5,%6,%7},{%8,%9},{%0,%1,%2,%3};"
        : "+f"(c[0]), "+f"(c[1]), "+f"(c[2]), "+f"(c[3])
        : "r"(a[0]), "r"(a[1]), "r"(a[2]), "r"(a[3]), "r"(b[0]), "r"(b[1]));
}

// ---------------------------------------------------------------------------
// FP16 mma.sync GEMM (fp32 accum), CTA 128x128, 256 threads = 8 warps (4m x 2n),
// warp tile 32x64, BK=64, 3-stage cp.async pipeline, ldmatrix operands.
// MODE 0: fused QKV proj; grid.x=48: sel=bx>>4 picks Wq/Wk/Wv, head=bx&15.
// MODE 3: out proj C = ctx * Wo^T + bias, fp32 out.
// ---------------------------------------------------------------------------
#define BK 64
#define SA_H 72                                 // tile row stride (halves)
#define B_OFF_H (128 * SA_H)                    // halves
#define STAGE_H (2 * 128 * SA_H)                // 18432 halves = 36864 B
#define NSTAGE 3
#define SMEM_BYTES (NSTAGE * STAGE_H * 2)       // 110592

template<int MODE>
__global__ __launch_bounds__(256, 2)
void gemm_tc(float* __restrict__ Oext, const float* __restrict__ bias)
{
    extern __shared__ __align__(16) char dynRaw[];
    __half* dynh = (__half*)dynRaw;

    const int tid  = threadIdx.x;
    const int wid  = tid >> 5;
    const int lane = tid & 31;
    const int wr   = wid >> 1;     // 4 m-groups of 32
    const int wc   = wid & 1;      // 2 n-groups of 64
    const int m0   = blockIdx.y * 128;
    const int sel  = (MODE == 0) ? (blockIdx.x >> 4) : 0;
    const int n0   = (MODE == 0) ? (blockIdx.x & 15) * 128 : blockIdx.x * 128;

    const __half* A;
    const __half* Bm;
    if (MODE == 0) { A = g_xh;   Bm = g_wh[sel]; }
    else           { A = g_ctxh; Bm = g_wh[3]; }
    const int T = EMB / BK;

    const uint32_t sbase = smem_u32(dynh);

    auto load_stage = [&](int buf, int t) {
        const int k0 = t * BK;
        const uint32_t sa = sbase + (uint32_t)(buf * STAGE_H) * 2u;
        #pragma unroll
        for (int i = 0; i < 4; i++) {
            int id = tid + i * 256;
            int r = id >> 3, c8 = id & 7;
            cp16(sa + (uint32_t)(r * SA_H + c8 * 8) * 2u,
                 A + (size_t)(m0 + r) * EMB + k0 + c8 * 8);
        }
        #pragma unroll
        for (int i = 0; i < 4; i++) {
            int id = tid + i * 256;
            int r = id >> 3, c8 = id & 7;
            cp16(sa + (uint32_t)(B_OFF_H + r * SA_H + c8 * 8) * 2u,
                 Bm + (size_t)(n0 + r) * EMB + k0 + c8 * 8);
        }
        asm volatile("cp.async.commit_group;\n");
    };

    float acc[2][8][4];
    #pragma unroll
    for (int i = 0; i < 2; i++)
        #pragma unroll
        for (int j = 0; j < 8; j++)
            #pragma unroll
            for (int e = 0; e < 4; e++) acc[i][j][e] = 0.0f;

    load_stage(0, 0);
    load_stage(1, 1);

    const int a_rsel = (lane & 7) + ((lane >> 3) & 1) * 8;
    const int a_ksel = ((lane >> 4) & 1) * 8;
    const int b_nsel = (lane & 7) + ((lane >> 4) & 1) * 8;
    const int b_ksel = ((lane >> 3) & 1) * 8;

    for (int t = 0; t < T; t++) {
        asm volatile("cp.async.wait_group 1;\n" ::: "memory");
        __syncthreads();

        if (t + 2 < T) load_stage((t + 2) % NSTAGE, t + 2);
        else asm volatile("cp.async.commit_group;\n");

        const uint32_t st = sbase + (uint32_t)((t % NSTAGE) * STAGE_H) * 2u;

        #pragma unroll
        for (int ks = 0; ks < 4; ks++) {
            uint32_t a[2][4], b[8][2];
            #pragma unroll
            for (int i = 0; i < 2; i++)
                ldsm4(a[i], st + (uint32_t)((wr * 32 + i * 16 + a_rsel) * SA_H
                                            + ks * 16 + a_ksel) * 2u);
            #pragma unroll
            for (int u = 0; u < 4; u++) {
                uint32_t r[4];
                ldsm4(r, st + (uint32_t)(B_OFF_H + (wc * 64 + u * 16 + b_nsel) * SA_H
                                         + ks * 16 + b_ksel) * 2u);
                b[2 * u][0] = r[0]; b[2 * u][1] = r[1];
                b[2 * u + 1][0] = r[2]; b[2 * u + 1][1] = r[3];
            }
            #pragma unroll
            for (int i = 0; i < 2; i++)
                #pragma unroll
                for (int j = 0; j < 8; j++)
                    mma_f16(acc[i][j], a[i], b[j]);
        }
    }

    const int er = lane >> 2;
    const int ec = (lane & 3) * 2;

    if (MODE == 3) {
        float* base = Oext + (size_t)m0 * EMB + n0;
        #pragma unroll
        for (int i = 0; i < 2; i++)
            #pragma unroll
            for (int j = 0; j < 8; j++) {
                int lrow = wr * 32 + i * 16 + er;
                int lcol = wc * 64 + j * 8 + ec;
                float b0 = bias[n0 + lcol], b1 = bias[n0 + lcol + 1];
                *(float2*)(base + (size_t)lrow * EMB + lcol) =
                    make_float2(acc[i][j][0] + b0, acc[i][j][1] + b1);
                *(float2*)(base + (size_t)(lrow + 8) * EMB + lcol) =
                    make_float2(acc[i][j][2] + b0, acc[i][j][3] + b1);
            }
    } else {
        int b = m0 >> 11;
        __half* qkv = (sel == 0 ? g_qh : sel == 1 ? g_kh : g_vh);
        __half* hb = qkv + ((size_t)(b * NH + (blockIdx.x & 15))) * SD
                     + (size_t)(m0 & (SEQ - 1)) * DH;
        #pragma unroll
        for (int i = 0; i < 2; i++)
            #pragma unroll
            for (int j = 0; j < 8; j++) {
                int lrow = wr * 32 + i * 16 + er;
                int lcol = wc * 64 + j * 8 + ec;
                *(__half2*)(hb + (size_t)lrow * DH + lcol) =
                    __floats2half2_rn(acc[i][j][0], acc[i][j][1]);
                *(__half2*)(hb + (size_t)(lrow + 8) * DH + lcol) =
                    __floats2half2_rn(acc[i][j][2], acc[i][j][3]);
            }
    }
}

// ---------------------------------------------------------------------------
// Flash attention: ctx = softmax(Q K^T / sqrt(dh), causal) V  in ONE kernel.
// CTA = (q-tile of 128 rows, bh). 8 warps x 16 rows each (warp owns full S
// rows so P stays register-local for the PV MMA). KV streamed in 64-wide
// chunks, double-buffered cp.async. Online softmax (m,l) in registers;
// O rescaled per chunk. P repacked from S accumulators via the C->A
// fragment identity. qt = 15-bx: longest jobs first.
// ---------------------------------------------------------------------------
#define FQ_SA 136
#define FK_SA 136
#define FV_SA 72
#define FQ_W (128 * FQ_SA)                   // 17408 halves
#define FK_W (64 * FK_SA)                    // 8704
#define FV_W (128 * FV_SA)                   // 9216
#define OFF_K FQ_W
#define OFF_V (OFF_K + 2 * FK_W)
#define FLASH_SMEM ((OFF_V + 2 * FV_W) * 2)  // 106496 B

__global__ __launch_bounds__(256, 2)
void flash_attn()
{
    extern __shared__ __align__(16) char dynRaw[];
    __half* sm = (__half*)dynRaw;

    const int tid  = threadIdx.x;
    const int wid  = tid >> 5;
    const int lane = tid & 31;
    const int qt   = 15 - blockIdx.x;
    const int z    = blockIdx.y;
    const int m0   = qt * 128;

    const __half* Q  = g_qh + (size_t)z * SD;
    const __half* K  = g_kh + (size_t)z * SD;
    const __half* VT = g_vth + (size_t)z * SD;
    const uint32_t sb = smem_u32(sm);

    // Q panel: 128 rows x 128 halves = 2048 16B chunks, 8/thread
    #pragma unroll
    for (int i = 0; i < 8; i++) {
        int id = tid + i * 256;
        int r = id >> 4, c8 = id & 15;
        cp16(sb + (uint32_t)(r * FQ_SA + c8 * 8) * 2u,
             Q + (size_t)(m0 + r) * DH + c8 * 8);
    }
    asm volatile("cp.async.commit_group;\n");

    const int NJ = 2 * (qt + 1);

    auto load_kv = [&](int j) {
        const int c0 = j * 64;
        const int buf = j & 1;
        // K chunk: 64 seq rows x 128 dh halves = 1024 chunks, 4/thread
        #pragma unroll
        for (int i = 0; i < 4; i++) {
            int id = tid + i * 256;
            int r = id >> 4, c8 = id & 15;
            cp16(sb + (uint32_t)(OFF_K + buf * FK_W + r * FK_SA + c8 * 8) * 2u,
                 K + (size_t)(c0 + r) * DH + c8 * 8);
        }
        // V^T chunk: 128 dh rows x 64 seq halves = 1024 chunks, 4/thread
        #pragma unroll
        for (int i = 0; i < 4; i++) {
            int id = tid + i * 256;
            int r = id >> 3, c8 = id & 7;
            cp16(sb + (uint32_t)(OFF_V + buf * FV_W + r * FV_SA + c8 * 8) * 2u,
                 VT + (size_t)r * SEQ + c0 + c8 * 8);
        }
        asm volatile("cp.async.commit_group;\n");
    };

    load_kv(0);

    float oacc[16][4];
    #pragma unroll
    for (int u = 0; u < 16; u++)
        #pragma unroll
        for (int e = 0; e < 4; e++) oacc[u][e] = 0.0f;
    float mrow[2] = {-1e30f, -1e30f};
    float lrow[2] = {0.0f, 0.0f};

    const int a_rsel = (lane & 7) + ((lane >> 3) & 1) * 8;
    const int a_ksel = ((lane >> 4) & 1) * 8;
    const int b_nsel = (lane & 7) + ((lane >> 4) & 1) * 8;
    const int b_ksel = ((lane >> 3) & 1) * 8;
    const int er = lane >> 2;
    const int ec = (lane & 3) * 2;

    for (int j = 0; j < NJ; j++) {
        asm volatile("cp.async.wait_group 0;\n" ::: "memory");
        __syncthreads();
        if (j + 1 < NJ) load_kv(j + 1);

        const int c0 = j * 64;
        const int buf = j & 1;
        const uint32_t kb = sb + (uint32_t)(OFF_K + buf * FK_W) * 2u;
        const uint32_t vb = sb + (uint32_t)(OFF_V + buf * FV_W) * 2u;

        // ---- phase A: S = Q x K_chunk^T (warp: 16 rows x 64 cols) ----
        float sacc[8][4];
        #pragma unroll
        for (int u = 0; u < 8; u++)
            #pragma unroll
            for (int e = 0; e < 4; e++) sacc[u][e] = 0.0f;

        #pragma unroll
        for (int ks = 0; ks < 8; ks++) {
            uint32_t a[4], b[8][2];
            ldsm4(a, sb + (uint32_t)((wid * 16 + a_rsel) * FQ_SA + ks * 16 + a_ksel) * 2u);
            #pragma unroll
            for (int u2 = 0; u2 < 4; u2++) {
                uint32_t r[4];
                ldsm4(r, kb + (uint32_t)((u2 * 16 + b_nsel) * FK_SA + ks * 16 + b_ksel) * 2u);
                b[2 * u2][0] = r[0]; b[2 * u2][1] = r[1];
                b[2 * u2 + 1][0] = r[2]; b[2 * u2 + 1][1] = r[3];
            }
            #pragma unroll
            for (int u = 0; u < 8; u++)
                mma_f16(sacc[u], a, b[u]);
        }

        // ---- phase B: online softmax (two rows per thread: er, er+8) ----
        const bool domask = (c0 + 63 > m0 + wid * 16);
        #pragma unroll
        for (int h = 0; h < 2; h++) {
            const int grow = m0 + wid * 16 + er + h * 8;
            // masked row max
            float cm = -1e30f;
            #pragma unroll
            for (int u = 0; u < 8; u++) {
                int c = c0 + u * 8 + ec;
                float x0 = sacc[u][h * 2], x1 = sacc[u][h * 2 + 1];
                if (domask) {
                    if (c > grow)     x0 = -1e30f;
                    if (c + 1 > grow) x1 = -1e30f;
                }
                cm = fmaxf(cm, fmaxf(x0, x1));
            }
            cm = fmaxf(cm, __shfl_xor_sync(0xFFFFFFFFu, cm, 1));
            cm = fmaxf(cm, __shfl_xor_sync(0xFFFFFFFFu, cm, 2));
            float mnew = fmaxf(mrow[h], cm);
            float scale = __expf((mrow[h] - mnew) * INVSQ);
            // exp + write P back into sacc
            float sum = 0.0f;
            #pragma unroll
            for (int u = 0; u < 8; u++) {
                int c = c0 + u * 8 + ec;
                float x0 = sacc[u][h * 2], x1 = sacc[u][h * 2 + 1];
                float p0 = (!domask || c     <= grow) ? __expf((x0 - mnew) * INVSQ) : 0.0f;
                float p1 = (!domask || c + 1 <= grow) ? __expf((x1 - mnew) * INVSQ) : 0.0f;
                sacc[u][h * 2] = p0; sacc[u][h * 2 + 1] = p1;
                sum += p0 + p1;
            }
            sum += __shfl_xor_sync(0xFFFFFFFFu, sum, 1);
            sum += __shfl_xor_sync(0xFFFFFFFFu, sum, 2);
            lrow[h] = lrow[h] * scale + sum;
            mrow[h] = mnew;
            // rescale O rows
            #pragma unroll
            for (int u = 0; u < 16; u++) {
                oacc[u][h * 2] *= scale; oacc[u][h * 2 + 1] *= scale;
            }
        }

        // ---- phase C: O += P x V_chunk (4 k16 steps) ----
        #pragma unroll
        for (int s = 0; s < 4; s++) {
            uint32_t pa[4];
            {
                __half2 t0 = __floats2half2_rn(sacc[2 * s][0], sacc[2 * s][1]);
                __half2 t1 = __floats2half2_rn(sacc[2 * s][2], sacc[2 * s][3]);
                __half2 t2 = __floats2half2_rn(sacc[2 * s + 1][0], sacc[2 * s + 1][1]);
                __half2 t3 = __floats2half2_rn(sacc[2 * s + 1][2], sacc[2 * s + 1][3]);
                pa[0] = *reinterpret_cast<uint32_t*>(&t0);
                pa[1] = *reinterpret_cast<uint32_t*>(&t1);
                pa[2] = *reinterpret_cast<uint32_t*>(&t2);
                pa[3] = *reinterpret_cast<uint32_t*>(&t3);
            }
            #pragma unroll
            for (int u2 = 0; u2 < 8; u2++) {
                uint32_t r[4];
                ldsm4(r, vb + (uint32_t)((u2 * 16 + b_nsel) * FV_SA + s * 16 + b_ksel) * 2u);
                uint32_t b0[2] = {r[0], r[1]}, b1[2] = {r[2], r[3]};
                mma_f16(oacc[2 * u2], pa, b0);
                mma_f16(oacc[2 * u2 + 1], pa, b1);
            }
        }
    }

    // ---- epilogue: normalize and store ctx ----
    const float rl0 = 1.0f / lrow[0];
    const float rl1 = 1.0f / lrow[1];
    const int b = z >> 4, hh = z & 15;
    __half* ob = g_ctxh + (size_t)b * SEQ * EMB
                 + (size_t)(m0 + wid * 16 + er) * EMB + hh * DH;
    #pragma unroll
    for (int u = 0; u < 16; u++) {
        int col = u * 8 + ec;
        *(__half2*)(ob + col) =
            __floats2half2_rn(oacc[u][0] * rl0, oacc[u][1] * rl0);
        *(__half2*)(ob + (size_t)8 * EMB + col) =
            __floats2half2_rn(oacc[u][2] * rl1, oacc[u][3] * rl1);
    }
}

// ---------------------------------------------------------------------------
// convert inputs to fp16: x -> g_xh, Wq/Wk/Wv/Wo -> g_wh[0..3]
// ---------------------------------------------------------------------------
__global__ __launch_bounds__(256)
void cvt_inputs(const float4* __restrict__ x,  const float4* __restrict__ wq,
                const float4* __restrict__ wk, const float4* __restrict__ wv,
                const float4* __restrict__ wo)
{
    const int XC = BATCH * SEQ * EMB / 4;
    const int WC = EMB * EMB / 4;
    int i = blockIdx.x * 256 + threadIdx.x;
    float4 v; __half* dst;
    if (i < XC) { v = x[i]; dst = g_xh + (size_t)i * 4; }
    else {
        int r = i - XC;
        int s = r / WC, o = r - s * WC;
        const float4* w = (s == 0 ? wq : s == 1 ? wk : s == 2 ? wv : wo);
        v = w[o]; dst = g_wh[s] + (size_t)o * 4;
    }
    *(__half2*)dst       = __floats2half2_rn(v.x, v.y);
    *(__half2*)(dst + 2) = __floats2half2_rn(v.z, v.w);
}

// ---------------------------------------------------------------------------
// V transpose: g_vh [bh][k][dh] -> g_vth [bh][dh][k], fp16 32x32 tiles
// ---------------------------------------------------------------------------
__global__ __launch_bounds__(256)
void transpose_v()
{
    __shared__ __half tile[32][33];
    const int z  = blockIdx.z;
    const int k0 = blockIdx.x * 32;
    const int n0 = blockIdx.y * 32;
    const int tx = threadIdx.x & 31;
    const int ty = threadIdx.x >> 5;

    const __half* src = g_vh + (size_t)z * SD;
    #pragma unroll
    for (int j = 0; j < 4; j++)
        tile[ty + j * 8][tx] = src[(size_t)(k0 + ty + j * 8) * DH + n0 + tx];
    __syncthreads();
    __half* dst = g_vth + (size_t)z * SD;
    #pragma unroll
    for (int j = 0; j < 4; j++)
        dst[(size_t)(n0 + ty + j * 8) * SEQ + k0 + tx] = tile[tx][ty + j * 8];
}

extern "C" void kernel_launch(void* const* d_in, const int* in_sizes, int n_in,
                              void* d_out, int out_size)
{
    const float* x  = (const float*)d_in[0];
    const float* Wq = (const float*)d_in[1];
    const float* Wk = (const float*)d_in[2];
    const float* Wv = (const float*)d_in[3];
    const float* Wo = (const float*)d_in[4];
    const float* bo = (const float*)d_in[5];
    float* out = (float*)d_out;

    cudaFuncSetAttribute(gemm_tc<0>, cudaFuncAttributeMaxDynamicSharedMemorySize, SMEM_BYTES);
    cudaFuncSetAttribute(gemm_tc<3>, cudaFuncAttributeMaxDynamicSharedMemorySize, SMEM_BYTES);
    cudaFuncSetAttribute(flash_attn, cudaFuncAttributeMaxDynamicSharedMemorySize, FLASH_SMEM);

    dim3 blk(256);
    const int XC = BATCH * SEQ * EMB / 4;
    const int WC = EMB * EMB / 4;

    // fp32 -> fp16 inputs
    cvt_inputs<<<(XC + 4 * WC) / 256, blk>>>((const float4*)x, (const float4*)Wq,
                                             (const float4*)Wk, (const float4*)Wv,
                                             (const float4*)Wo);

    // fused QKV: grid.x = 48 (3 weights x 16 head tiles)
    gemm_tc<0><<<dim3(48, 64, 1), blk, SMEM_BYTES>>>(nullptr, nullptr);

    // V transpose for flash's V^T operand
    transpose_v<<<dim3(SEQ / 32, DH / 32, BH), blk>>>();

    // flash attention: scores + softmax + PV in one kernel
    flash_attn<<<dim3(16, BH), blk, FLASH_SMEM>>>();

    // out = ctx Wo^T + bias (fp32 out)
    gemm_tc<3><<<dim3(16, 64, 1), blk, SMEM_BYTES>>>(out, bo);
}

// round 17
// speedup vs baseline: 1.3578x; 1.0095x over previous
#include <cuda_runtime.h>
#include <cuda_fp16.h>
#include <cstdint>

// ---------------- problem constants ----------------
#define BATCH 4
#define SEQ 2048
#define EMB 2048
#define NH 16
#define DH 128
#define BH (BATCH * NH)          // 64
#define SD (SEQ * DH)            // 262144
#define SS ((size_t)SEQ * SEQ)
#define INVSQ 0.08838834764831845f   // 1/sqrt(128)
#define LOG2E 1.4426950408889634f

// scratch (allocation-free rule)
__device__ __half g_xh[(size_t)BATCH * SEQ * EMB];
__device__ __half g_wh[4][(size_t)EMB * EMB];
__device__ __half g_qh[(size_t)BH * SD];            // Q pre-scaled by 1/sqrt(dh)
__device__ __half g_kh[(size_t)BH * SD];
__device__ __half g_vh[(size_t)BH * SD];
__device__ __half g_vth[(size_t)BH * SD];           // V transposed: [bh][dh][seq]
__device__ __half g_ctxh[(size_t)BATCH * SEQ * EMB];

__device__ __forceinline__ uint32_t smem_u32(const void* p) {
    return (uint32_t)__cvta_generic_to_shared(p);
}
__device__ __forceinline__ void cp16(uint32_t s, const void* g) {
    asm volatile("cp.async.cg.shared.global [%0], [%1], 16;\n" :: "r"(s), "l"(g));
}
__device__ __forceinline__ void ldsm4(uint32_t* r, uint32_t addr) {
    asm volatile("ldmatrix.sync.aligned.m8n8.x4.shared.b16 {%0,%1,%2,%3}, [%4];"
                 : "=r"(r[0]), "=r"(r[1]), "=r"(r[2]), "=r"(r[3]) : "r"(addr));
}
__device__ __forceinline__ void mma_f16(float* c, const uint32_t* a, const uint32_t* b) {
    asm volatile(
        "mma.sync.aligned.m16n8k16.row.col.f32.f16.f16.f32 "
        "{%0,%1,%2,%3},{%4,%5,%6,%7},{%8,%9},{%0,%1,%2,%3};"
        : "+f"(c[0]), "+f"(c[1]), "+f"(c[2]), "+f"(c[3])
        : "r"(a[0]), "r"(a[1]), "r"(a[2]), "r"(a[3]), "r"(b[0]), "r"(b[1]));
}

// ---------------------------------------------------------------------------
// FP16 mma.sync GEMM (fp32 accum), CTA 128x128, 256 threads = 8 warps (4m x 2n),
// warp tile 32x64, BK=64, 3-stage cp.async pipeline, ldmatrix operands.
// MODE 0: fused QKV proj; grid.x=48: sel=bx>>4 picks Wq/Wk/Wv, head=bx&15.
//         Q outputs pre-scaled by 1/sqrt(dh).
// MODE 3: out proj C = ctx * Wo^T + bias, fp32 out.
// ---------------------------------------------------------------------------
#define BK 64
#define SA_H 72                                 // tile row stride (halves)
#define B_OFF_H (128 * SA_H)                    // halves
#define STAGE_H (2 * 128 * SA_H)                // 18432 halves = 36864 B
#define NSTAGE 3
#define SMEM_BYTES (NSTAGE * STAGE_H * 2)       // 110592

template<int MODE>
__global__ __launch_bounds__(256, 2)
void gemm_tc(float* __restrict__ Oext, const float* __restrict__ bias)
{
    extern __shared__ __align__(16) char dynRaw[];
    __half* dynh = (__half*)dynRaw;

    const int tid  = threadIdx.x;
    const int wid  = tid >> 5;
    const int lane = tid & 31;
    const int wr   = wid >> 1;     // 4 m-groups of 32
    const int wc   = wid & 1;      // 2 n-groups of 64
    const int m0   = blockIdx.y * 128;
    const int sel  = (MODE == 0) ? (blockIdx.x >> 4) : 0;
    const int n0   = (MODE == 0) ? (blockIdx.x & 15) * 128 : blockIdx.x * 128;

    const __half* A;
    const __half* Bm;
    if (MODE == 0) { A = g_xh;   Bm = g_wh[sel]; }
    else           { A = g_ctxh; Bm = g_wh[3]; }
    const int T = EMB / BK;

    const uint32_t sbase = smem_u32(dynh);

    auto load_stage = [&](int buf, int t) {
        const int k0 = t * BK;
        const uint32_t sa = sbase + (uint32_t)(buf * STAGE_H) * 2u;
        #pragma unroll
        for (int i = 0; i < 4; i++) {
            int id = tid + i * 256;
            int r = id >> 3, c8 = id & 7;
            cp16(sa + (uint32_t)(r * SA_H + c8 * 8) * 2u,
                 A + (size_t)(m0 + r) * EMB + k0 + c8 * 8);
        }
        #pragma unroll
        for (int i = 0; i < 4; i++) {
            int id = tid + i * 256;
            int r = id >> 3, c8 = id & 7;
            cp16(sa + (uint32_t)(B_OFF_H + r * SA_H + c8 * 8) * 2u,
                 Bm + (size_t)(n0 + r) * EMB + k0 + c8 * 8);
        }
        asm volatile("cp.async.commit_group;\n");
    };

    float acc[2][8][4];
    #pragma unroll
    for (int i = 0; i < 2; i++)
        #pragma unroll
        for (int j = 0; j < 8; j++)
            #pragma unroll
            for (int e = 0; e < 4; e++) acc[i][j][e] = 0.0f;

    load_stage(0, 0);
    load_stage(1, 1);

    const int a_rsel = (lane & 7) + ((lane >> 3) & 1) * 8;
    const int a_ksel = ((lane >> 4) & 1) * 8;
    const int b_nsel = (lane & 7) + ((lane >> 4) & 1) * 8;
    const int b_ksel = ((lane >> 3) & 1) * 8;

    for (int t = 0; t < T; t++) {
        asm volatile("cp.async.wait_group 1;\n" ::: "memory");
        __syncthreads();

        if (t + 2 < T) load_stage((t + 2) % NSTAGE, t + 2);
        else asm volatile("cp.async.commit_group;\n");

        const uint32_t st = sbase + (uint32_t)((t % NSTAGE) * STAGE_H) * 2u;

        #pragma unroll
        for (int ks = 0; ks < 4; ks++) {
            uint32_t a[2][4], b[8][2];
            #pragma unroll
            for (int i = 0; i < 2; i++)
                ldsm4(a[i], st + (uint32_t)((wr * 32 + i * 16 + a_rsel) * SA_H
                                            + ks * 16 + a_ksel) * 2u);
            #pragma unroll
            for (int u = 0; u < 4; u++) {
                uint32_t r[4];
                ldsm4(r, st + (uint32_t)(B_OFF_H + (wc * 64 + u * 16 + b_nsel) * SA_H
                                         + ks * 16 + b_ksel) * 2u);
                b[2 * u][0] = r[0]; b[2 * u][1] = r[1];
                b[2 * u + 1][0] = r[2]; b[2 * u + 1][1] = r[3];
            }
            #pragma unroll
            for (int i = 0; i < 2; i++)
                #pragma unroll
                for (int j = 0; j < 8; j++)
                    mma_f16(acc[i][j], a[i], b[j]);
        }
    }

    const int er = lane >> 2;
    const int ec = (lane & 3) * 2;

    if (MODE == 3) {
        float* base = Oext + (size_t)m0 * EMB + n0;
        #pragma unroll
        for (int i = 0; i < 2; i++)
            #pragma unroll
            for (int j = 0; j < 8; j++) {
                int lrow = wr * 32 + i * 16 + er;
                int lcol = wc * 64 + j * 8 + ec;
                float b0 = bias[n0 + lcol], b1 = bias[n0 + lcol + 1];
                *(float2*)(base + (size_t)lrow * EMB + lcol) =
                    make_float2(acc[i][j][0] + b0, acc[i][j][1] + b1);
                *(float2*)(base + (size_t)(lrow + 8) * EMB + lcol) =
                    make_float2(acc[i][j][2] + b0, acc[i][j][3] + b1);
            }
    } else {
        int b = m0 >> 11;
        __half* qkv = (sel == 0 ? g_qh : sel == 1 ? g_kh : g_vh);
        const float qs = (sel == 0) ? INVSQ : 1.0f;   // pre-scale Q
        __half* hb = qkv + ((size_t)(b * NH + (blockIdx.x & 15))) * SD
                     + (size_t)(m0 & (SEQ - 1)) * DH;
        #pragma unroll
        for (int i = 0; i < 2; i++)
            #pragma unroll
            for (int j = 0; j < 8; j++) {
                int lrow = wr * 32 + i * 16 + er;
                int lcol = wc * 64 + j * 8 + ec;
                *(__half2*)(hb + (size_t)lrow * DH + lcol) =
                    __floats2half2_rn(acc[i][j][0] * qs, acc[i][j][1] * qs);
                *(__half2*)(hb + (size_t)(lrow + 8) * DH + lcol) =
                    __floats2half2_rn(acc[i][j][2] * qs, acc[i][j][3] * qs);
            }
    }
}

// ---------------------------------------------------------------------------
// Flash attention: ctx = softmax(Q K^T, causal) V in ONE kernel.
// Q is pre-scaled by 1/sqrt(dh), so no scale inside softmax.
// CTA = (q-tile of 128 rows, bh). 8 warps x 16 rows each. KV streamed in
// 64-wide chunks, double-buffered cp.async. Online softmax with exp2
// (FFMA+EX2 per element) and conditional O-rescale (only when row max
// advances). qt = 15-bx: longest jobs first.
// ---------------------------------------------------------------------------
#define FQ_SA 136
#define FK_SA 136
#define FV_SA 72
#define FQ_W (128 * FQ_SA)                   // 17408 halves
#define FK_W (64 * FK_SA)                    // 8704
#define FV_W (128 * FV_SA)                   // 9216
#define OFF_K FQ_W
#define OFF_V (OFF_K + 2 * FK_W)
#define FLASH_SMEM ((OFF_V + 2 * FV_W) * 2)  // 106496 B

__global__ __launch_bounds__(256, 2)
void flash_attn()
{
    extern __shared__ __align__(16) char dynRaw[];
    __half* sm = (__half*)dynRaw;

    const int tid  = threadIdx.x;
    const int wid  = tid >> 5;
    const int lane = tid & 31;
    const int qt   = 15 - blockIdx.x;
    const int z    = blockIdx.y;
    const int m0   = qt * 128;

    const __half* Q  = g_qh + (size_t)z * SD;
    const __half* K  = g_kh + (size_t)z * SD;
    const __half* VT = g_vth + (size_t)z * SD;
    const uint32_t sb = smem_u32(sm);

    // Q panel: 128 rows x 128 halves = 2048 16B chunks, 8/thread
    #pragma unroll
    for (int i = 0; i < 8; i++) {
        int id = tid + i * 256;
        int r = id >> 4, c8 = id & 15;
        cp16(sb + (uint32_t)(r * FQ_SA + c8 * 8) * 2u,
             Q + (size_t)(m0 + r) * DH + c8 * 8);
    }
    asm volatile("cp.async.commit_group;\n");

    const int NJ = 2 * (qt + 1);

    auto load_kv = [&](int j) {
        const int c0 = j * 64;
        const int buf = j & 1;
        #pragma unroll
        for (int i = 0; i < 4; i++) {
            int id = tid + i * 256;
            int r = id >> 4, c8 = id & 15;
            cp16(sb + (uint32_t)(OFF_K + buf * FK_W + r * FK_SA + c8 * 8) * 2u,
                 K + (size_t)(c0 + r) * DH + c8 * 8);
        }
        #pragma unroll
        for (int i = 0; i < 4; i++) {
            int id = tid + i * 256;
            int r = id >> 3, c8 = id & 7;
            cp16(sb + (uint32_t)(OFF_V + buf * FV_W + r * FV_SA + c8 * 8) * 2u,
                 VT + (size_t)r * SEQ + c0 + c8 * 8);
        }
        asm volatile("cp.async.commit_group;\n");
    };

    load_kv(0);

    float oacc[16][4];
    #pragma unroll
    for (int u = 0; u < 16; u++)
        #pragma unroll
        for (int e = 0; e < 4; e++) oacc[u][e] = 0.0f;
    float mrow[2] = {-1e30f, -1e30f};
    float lrow[2] = {0.0f, 0.0f};

    const int a_rsel = (lane & 7) + ((lane >> 3) & 1) * 8;
    const int a_ksel = ((lane >> 4) & 1) * 8;
    const int b_nsel = (lane & 7) + ((lane >> 4) & 1) * 8;
    const int b_ksel = ((lane >> 3) & 1) * 8;
    const int er = lane >> 2;
    const int ec = (lane & 3) * 2;

    for (int j = 0; j < NJ; j++) {
        asm volatile("cp.async.wait_group 0;\n" ::: "memory");
        __syncthreads();
        if (j + 1 < NJ) load_kv(j + 1);

        const int c0 = j * 64;
        const int buf = j & 1;
        const uint32_t kb = sb + (uint32_t)(OFF_K + buf * FK_W) * 2u;
        const uint32_t vb = sb + (uint32_t)(OFF_V + buf * FV_W) * 2u;

        // ---- phase A: S = Q x K_chunk^T (warp: 16 rows x 64 cols) ----
        float sacc[8][4];
        #pragma unroll
        for (int u = 0; u < 8; u++)
            #pragma unroll
            for (int e = 0; e < 4; e++) sacc[u][e] = 0.0f;

        #pragma unroll
        for (int ks = 0; ks < 8; ks++) {
            uint32_t a[4], b[8][2];
            ldsm4(a, sb + (uint32_t)((wid * 16 + a_rsel) * FQ_SA + ks * 16 + a_ksel) * 2u);
            #pragma unroll
            for (int u2 = 0; u2 < 4; u2++) {
                uint32_t r[4];
                ldsm4(r, kb + (uint32_t)((u2 * 16 + b_nsel) * FK_SA + ks * 16 + b_ksel) * 2u);
                b[2 * u2][0] = r[0]; b[2 * u2][1] = r[1];
                b[2 * u2 + 1][0] = r[2]; b[2 * u2 + 1][1] = r[3];
            }
            #pragma unroll
            for (int u = 0; u < 8; u++)
                mma_f16(sacc[u], a, b[u]);
        }

        // ---- phase B: online softmax (rows er, er+8); exp2-based ----
        const bool domask = (c0 + 63 > m0 + wid * 16);
        #pragma unroll
        for (int h = 0; h < 2; h++) {
            const int grow = m0 + wid * 16 + er + h * 8;
            float cm = -1e30f;
            #pragma unroll
            for (int u = 0; u < 8; u++) {
                int c = c0 + u * 8 + ec;
                float x0 = sacc[u][h * 2], x1 = sacc[u][h * 2 + 1];
                if (domask) {
                    if (c > grow)     x0 = -1e30f;
                    if (c + 1 > grow) x1 = -1e30f;
                }
                cm = fmaxf(cm, fmaxf(x0, x1));
            }
            cm = fmaxf(cm, __shfl_xor_sync(0xFFFFFFFFu, cm, 1));
            cm = fmaxf(cm, __shfl_xor_sync(0xFFFFFFFFu, cm, 2));

            if (cm > mrow[h]) {     // row max advanced: rescale state
                float scale = exp2f((mrow[h] - cm) * LOG2E);
                lrow[h] *= scale;
                #pragma unroll
                for (int u = 0; u < 16; u++) {
                    oacc[u][h * 2] *= scale; oacc[u][h * 2 + 1] *= scale;
                }
                mrow[h] = cm;
            }
            const float mb = mrow[h] * LOG2E;

            float sum = 0.0f;
            #pragma unroll
            for (int u = 0; u < 8; u++) {
                int c = c0 + u * 8 + ec;
                float x0 = sacc[u][h * 2], x1 = sacc[u][h * 2 + 1];
                float p0 = (!domask || c     <= grow) ? exp2f(fmaf(x0, LOG2E, -mb)) : 0.0f;
                float p1 = (!domask || c + 1 <= grow) ? exp2f(fmaf(x1, LOG2E, -mb)) : 0.0f;
                sacc[u][h * 2] = p0; sacc[u][h * 2 + 1] = p1;
                sum += p0 + p1;
            }
            sum += __shfl_xor_sync(0xFFFFFFFFu, sum, 1);
            sum += __shfl_xor_sync(0xFFFFFFFFu, sum, 2);
            lrow[h] += sum;
        }

        // ---- phase C: O += P x V_chunk (4 k16 steps) ----
        #pragma unroll
        for (int s = 0; s < 4; s++) {
            uint32_t pa[4];
            {
                __half2 t0 = __floats2half2_rn(sacc[2 * s][0], sacc[2 * s][1]);
                __half2 t1 = __floats2half2_rn(sacc[2 * s][2], sacc[2 * s][3]);
                __half2 t2 = __floats2half2_rn(sacc[2 * s + 1][0], sacc[2 * s + 1][1]);
                __half2 t3 = __floats2half2_rn(sacc[2 * s + 1][2], sacc[2 * s + 1][3]);
                pa[0] = *reinterpret_cast<uint32_t*>(&t0);
                pa[1] = *reinterpret_cast<uint32_t*>(&t1);
                pa[2] = *reinterpret_cast<uint32_t*>(&t2);
                pa[3] = *reinterpret_cast<uint32_t*>(&t3);
            }
            #pragma unroll
            for (int u2 = 0; u2 < 8; u2++) {
                uint32_t r[4];
                ldsm4(r, vb + (uint32_t)((u2 * 16 + b_nsel) * FV_SA + s * 16 + b_ksel) * 2u);
                uint32_t b0[2] = {r[0], r[1]}, b1[2] = {r[2], r[3]};
                mma_f16(oacc[2 * u2], pa, b0);
                mma_f16(oacc[2 * u2 + 1], pa, b1);
            }
        }
    }

    // ---- epilogue: normalize and store ctx ----
    const float rl0 = 1.0f / lrow[0];
    const float rl1 = 1.0f / lrow[1];
    const int b = z >> 4, hh = z & 15;
    __half* ob = g_ctxh + (size_t)b * SEQ * EMB
                 + (size_t)(m0 + wid * 16 + er) * EMB + hh * DH;
    #pragma unroll
    for (int u = 0; u < 16; u++) {
        int col = u * 8 + ec;
        *(__half2*)(ob + col) =
            __floats2half2_rn(oacc[u][0] * rl0, oacc[u][1] * rl0);
        *(__half2*)(ob + (size_t)8 * EMB + col) =
            __floats2half2_rn(oacc[u][2] * rl1, oacc[u][3] * rl1);
    }
}

// ---------------------------------------------------------------------------
// convert inputs to fp16: x -> g_xh, Wq/Wk/Wv/Wo -> g_wh[0..3]
// ---------------------------------------------------------------------------
__global__ __launch_bounds__(256)
void cvt_inputs(const float4* __restrict__ x,  const float4* __restrict__ wq,
                const float4* __restrict__ wk, const float4* __restrict__ wv,
                const float4* __restrict__ wo)
{
    const int XC = BATCH * SEQ * EMB / 4;
    const int WC = EMB * EMB / 4;
    int i = blockIdx.x * 256 + threadIdx.x;
    float4 v; __half* dst;
    if (i < XC) { v = x[i]; dst = g_xh + (size_t)i * 4; }
    else {
        int r = i - XC;
        int s = r / WC, o = r - s * WC;
        const float4* w = (s == 0 ? wq : s == 1 ? wk : s == 2 ? wv : wo);
        v = w[o]; dst = g_wh[s] + (size_t)o * 4;
    }
    *(__half2*)dst       = __floats2half2_rn(v.x, v.y);
    *(__half2*)(dst + 2) = __floats2half2_rn(v.z, v.w);
}

// ---------------------------------------------------------------------------
// V transpose: g_vh [bh][k][dh] -> g_vth [bh][dh][k], fp16 32x32 tiles
// ---------------------------------------------------------------------------
__global__ __launch_bounds__(256)
void transpose_v()
{
    __shared__ __half tile[32][33];
    const int z  = blockIdx.z;
    const int k0 = blockIdx.x * 32;
    const int n0 = blockIdx.y * 32;
    const int tx = threadIdx.x & 31;
    const int ty = threadIdx.x >> 5;

    const __half* src = g_vh + (size_t)z * SD;
    #pragma unroll
    for (int j = 0; j < 4; j++)
        tile[ty + j * 8][tx] = src[(size_t)(k0 + ty + j * 8) * DH + n0 + tx];
    __syncthreads();
    __half* dst = g_vth + (size_t)z * SD;
    #pragma unroll
    for (int j = 0; j < 4; j++)
        dst[(size_t)(n0 + ty + j * 8) * SEQ + k0 + tx] = tile[tx][ty + j * 8];
}

extern "C" void kernel_launch(void* const* d_in, const int* in_sizes, int n_in,
                              void* d_out, int out_size)
{
    const float* x  = (const float*)d_in[0];
    const float* Wq = (const float*)d_in[1];
    const float* Wk = (const float*)d_in[2];
    const float* Wv = (const float*)d_in[3];
    const float* Wo = (const float*)d_in[4];
    const float* bo = (const float*)d_in[5];
    float* out = (float*)d_out;

    cudaFuncSetAttribute(gemm_tc<0>, cudaFuncAttributeMaxDynamicSharedMemorySize, SMEM_BYTES);
    cudaFuncSetAttribute(gemm_tc<3>, cudaFuncAttributeMaxDynamicSharedMemorySize, SMEM_BYTES);
    cudaFuncSetAttribute(flash_attn, cudaFuncAttributeMaxDynamicSharedMemorySize, FLASH_SMEM);

    dim3 blk(256);
    const int XC = BATCH * SEQ * EMB / 4;
    const int WC = EMB * EMB / 4;

    // fp32 -> fp16 inputs
    cvt_inputs<<<(XC + 4 * WC) / 256, blk>>>((const float4*)x, (const float4*)Wq,
                                             (const float4*)Wk, (const float4*)Wv,
                                             (const float4*)Wo);

    // fused QKV: grid.x = 48 (3 weights x 16 head tiles); Q pre-scaled
    gemm_tc<0><<<dim3(48, 64, 1), blk, SMEM_BYTES>>>(nullptr, nullptr);

    // V transpose for flash's V^T operand
    transpose_v<<<dim3(SEQ / 32, DH / 32, BH), blk>>>();

    // flash attention: scores + softmax + PV in one kernel
    flash_attn<<<dim3(16, BH), blk, FLASH_SMEM>>>();

    // out = ctx Wo^T + bias (fp32 out)
    gemm_tc<3><<<dim3(16, 64, 1), blk, SMEM_BYTES>>>(out, bo);
}